// round 7
// baseline (speedup 1.0000x reference)
#include <cuda_runtime.h>
#include <math.h>

// Reservoir step:
//   state = W @ r + W_in @ u + W_fb @ y_prev          [8192]
//   r_new = r + (DT/TAU) * (tanh(state) - r)          [8192]
//   out   = W_out @ r_new                             [32]
//
// Inputs (metadata order):
//   d_in[0] input_signal [64]        f32
//   d_in[1] W            [8192*8192] f32 row-major
//   d_in[2] W_in         [8192*64]   f32 row-major
//   d_in[3] W_fb         [8192*32]   f32 row-major
//   d_in[4] W_out        [32*8192]   f32 row-major
//   d_in[5] r            [8192]      f32
//   d_in[6] out_prev     [32]        f32
// Output: [32] f32

#define DIM_RES 8192
#define DIM_IN  64
#define DIM_OUT 32
#define LEAK    (0.1f / 10.0f)   // DT / TAU

// scratch for r_new between kernels (no cudaMalloc allowed)
__device__ float g_rnew[DIM_RES];

// ---------------------------------------------------------------------------
// Kernel 1: fused  state -> tanh -> leaky update -> g_rnew
// 1024 blocks x 256 threads; one warp per reservoir row.
// r is staged in shared memory (32 KB) so only W streams from DRAM.
// ---------------------------------------------------------------------------
__global__ __launch_bounds__(256, 6)
void reservoir_update_kernel(const float* __restrict__ W,
                             const float* __restrict__ W_in,
                             const float* __restrict__ W_fb,
                             const float* __restrict__ r,
                             const float* __restrict__ u,
                             const float* __restrict__ y_prev)
{
    __shared__ float4 sr[DIM_RES / 4];   // 8192 floats = 32 KB

    const int tid  = threadIdx.x;
    const int lane = tid & 31;
    const int wid  = tid >> 5;

    // cooperative load of r into shared (coalesced float4; r is L2-resident)
    const float4* r4 = reinterpret_cast<const float4*>(r);
    #pragma unroll
    for (int t = 0; t < (DIM_RES / 4) / 256; ++t) {
        sr[tid + t * 256] = r4[tid + t * 256];
    }
    __syncthreads();

    const int row = blockIdx.x * 8 + wid;   // 1024 blocks * 8 warps = 8192 rows

    // main dot: W[row,:] . r   -- 64 iterations of float4 per lane
    const float4* Wrow = reinterpret_cast<const float4*>(W + (size_t)row * DIM_RES);
    float acc = 0.0f;
    #pragma unroll 8
    for (int it = 0; it < (DIM_RES / 4) / 32; ++it) {
        const int idx = it * 32 + lane;          // coalesced 128B per warp-step
        float4 w = __ldg(&Wrow[idx]);
        float4 v = sr[idx];
        acc = fmaf(w.x, v.x, acc);
        acc = fmaf(w.y, v.y, acc);
        acc = fmaf(w.z, v.z, acc);
        acc = fmaf(w.w, v.w, acc);
    }

    // small terms: W_in[row,:] @ u (64) + W_fb[row,:] @ y_prev (32)
    // lane l handles W_in cols {l, l+32} and W_fb col {l}
    {
        const float* wi = W_in + (size_t)row * DIM_IN;
        const float* wf = W_fb + (size_t)row * DIM_OUT;
        acc = fmaf(__ldg(&wi[lane]),      __ldg(&u[lane]),       acc);
        acc = fmaf(__ldg(&wi[lane + 32]), __ldg(&u[lane + 32]),  acc);
        acc = fmaf(__ldg(&wf[lane]),      __ldg(&y_prev[lane]),  acc);
    }

    // warp reduce
    #pragma unroll
    for (int off = 16; off > 0; off >>= 1)
        acc += __shfl_down_sync(0xFFFFFFFFu, acc, off);

    if (lane == 0) {
        // r[row] is already staged in shared — no extra global load
        float rv = reinterpret_cast<const float*>(sr)[row & (DIM_RES - 1)];
        float rn = rv + LEAK * (tanhf(acc) - rv);
        __stcg(&g_rnew[row], rn);    // keep in L2 for the readout kernel
    }
}

// ---------------------------------------------------------------------------
// Kernel 2: out = W_out @ r_new   (32 blocks, one output each; block reduce)
// ---------------------------------------------------------------------------
__global__ __launch_bounds__(256)
void readout_kernel(const float* __restrict__ W_out, float* __restrict__ out)
{
    __shared__ float red[8];

    const int o    = blockIdx.x;
    const int tid  = threadIdx.x;
    const int lane = tid & 31;
    const int wid  = tid >> 5;

    const float4* wo = reinterpret_cast<const float4*>(W_out + (size_t)o * DIM_RES);
    const float4* rn = reinterpret_cast<const float4*>(g_rnew);

    float acc = 0.0f;
    #pragma unroll
    for (int t = 0; t < (DIM_RES / 4) / 256; ++t) {   // 8 float4 per thread
        const int idx = tid + t * 256;
        float4 w = __ldg(&wo[idx]);
        float4 v = rn[idx];
        acc = fmaf(w.x, v.x, acc);
        acc = fmaf(w.y, v.y, acc);
        acc = fmaf(w.z, v.z, acc);
        acc = fmaf(w.w, v.w, acc);
    }

    #pragma unroll
    for (int off = 16; off > 0; off >>= 1)
        acc += __shfl_down_sync(0xFFFFFFFFu, acc, off);

    if (lane == 0) red[wid] = acc;
    __syncthreads();

    if (wid == 0) {
        float s = (lane < 8) ? red[lane] : 0.0f;
        #pragma unroll
        for (int off = 4; off > 0; off >>= 1)
            s += __shfl_down_sync(0xFFFFFFFFu, s, off);
        if (lane == 0) out[o] = s;
    }
}

// ---------------------------------------------------------------------------
extern "C" void kernel_launch(void* const* d_in, const int* in_sizes, int n_in,
                              void* d_out, int out_size)
{
    const float* u      = (const float*)d_in[0];
    const float* W      = (const float*)d_in[1];
    const float* W_in   = (const float*)d_in[2];
    const float* W_fb   = (const float*)d_in[3];
    const float* W_out  = (const float*)d_in[4];
    const float* r      = (const float*)d_in[5];
    const float* y_prev = (const float*)d_in[6];
    float* out = (float*)d_out;

    reservoir_update_kernel<<<DIM_RES / 8, 256>>>(W, W_in, W_fb, r, u, y_prev);
    readout_kernel<<<DIM_OUT, 256>>>(W_out, out);
}